// round 14
// baseline (speedup 1.0000x reference)
#include <cuda_runtime.h>
#include <cuda_bf16.h>
#include <math.h>
#include <stdint.h>

// Problem constants
#define BSZ 8
#define HW 32
#define DMODEL 128
#define NHEADS 8
#define SCALE 0.08838834764831845f   // 1/sqrt(128)
#define PS 68                         // smem row stride in uint32 (conflict-free: bank=4*gid+tig)

// ---------------------------------------------------------------- scratch
__device__ float g_x  [BSZ*HW*HW*DMODEL];            // LN output  (4 MB)
__device__ float g_q  [BSZ*HW*HW*NHEADS*DMODEL];     // 32 MB
__device__ float g_k  [BSZ*HW*HW*NHEADS*DMODEL];     // 32 MB
__device__ float g_ctx[BSZ*HW*HW*NHEADS*DMODEL];     // 32 MB
__device__ __nv_bfloat16 g_xth[BSZ*DMODEL*1024];     // x^T hi  (2 MB)  [b][d][n]
__device__ __nv_bfloat16 g_xtl[BSZ*DMODEL*1024];     // x^T lo  (2 MB)
__device__ float g_pscratch[67108864];               // fallback probs buffer

// fp32 pair -> bf16x2 (hi) + bf16x2 (residual lo)
__device__ __forceinline__ void split_pair(float x, float y, uint32_t& hi, uint32_t& lo) {
    __nv_bfloat16 hx = __float2bfloat16(x), hy = __float2bfloat16(y);
    float rx = x - __bfloat162float(hx), ry = y - __bfloat162float(hy);
    __nv_bfloat162 H; H.x = hx; H.y = hy;
    __nv_bfloat162 L; L.x = __float2bfloat16(rx); L.y = __float2bfloat16(ry);
    hi = *reinterpret_cast<uint32_t*>(&H);
    lo = *reinterpret_cast<uint32_t*>(&L);
}

// warp-level bf16 MMA, m16n8k16, fp32 accumulate (base PTX; works on sm_100).
// NOT volatile: lets the compiler schedule/interleave independent MMAs.
__device__ __forceinline__ void mma_bf16(float* d, const uint32_t* a, const uint32_t* b) {
    asm("mma.sync.aligned.m16n8k16.row.col.f32.bf16.bf16.f32 "
        "{%0,%1,%2,%3}, {%4,%5,%6,%7}, {%8,%9}, {%0,%1,%2,%3};"
        : "+f"(d[0]), "+f"(d[1]), "+f"(d[2]), "+f"(d[3])
        : "r"(a[0]), "r"(a[1]), "r"(a[2]), "r"(a[3]), "r"(b[0]), "r"(b[1]));
}

// ---------------------------------------------------------------- LayerNorm
__global__ void ln_kernel(const float* __restrict__ hs,
                          const float* __restrict__ gam,
                          const float* __restrict__ bet) {
    int row = blockIdx.x;          // 8192 rows
    int c   = threadIdx.x;         // 128
    float v = hs[row*128 + c];
    float s = v, s2 = v*v;
    #pragma unroll
    for (int o = 16; o >= 1; o >>= 1) {
        s  += __shfl_xor_sync(0xffffffffu, s,  o);
        s2 += __shfl_xor_sync(0xffffffffu, s2, o);
    }
    __shared__ float ws[4], ws2[4];
    int w = c >> 5;
    if ((c & 31) == 0) { ws[w] = s; ws2[w] = s2; }
    __syncthreads();
    s  = ws[0] + ws[1] + ws[2] + ws[3];
    s2 = ws2[0] + ws2[1] + ws2[2] + ws2[3];
    float mu  = s  * (1.0f/128.0f);
    float var = s2 * (1.0f/128.0f) - mu*mu;
    float r   = rsqrtf(var + 1e-5f);
    g_x[row*128 + c] = (v - mu) * r * gam[c] + bet[c];
}

// -------------------------------------------- x transpose -> bf16 hi/lo [b][d][n]
__global__ void __launch_bounds__(256) xt_kernel() {
    __shared__ float sm[32][33];
    int nt = blockIdx.x, dt = blockIdx.y, b = blockIdx.z;
    int t = threadIdx.x;
    #pragma unroll
    for (int it = 0; it < 4; it++) {
        int tn = (t >> 5) + it*8, td = t & 31;
        sm[tn][td] = g_x[((size_t)b*1024 + nt*32 + tn)*128 + dt*32 + td];
    }
    __syncthreads();
    #pragma unroll
    for (int it = 0; it < 2; it++) {
        int w = t + it*256;
        int td = w >> 4, np = w & 15;
        uint32_t hi, lo;
        split_pair(sm[2*np][td], sm[2*np+1][td], hi, lo);
        size_t off = ((size_t)b*128 + dt*32 + td)*1024 + nt*32 + 2*np;
        *reinterpret_cast<uint32_t*>(&g_xth[off]) = hi;
        *reinterpret_cast<uint32_t*>(&g_xtl[off]) = lo;
    }
}

// ================================================ tensorized Q,K projection
#define QK_AH   0
#define QK_AL   34816
#define QK_BH   69632
#define QK_BL   104448
#define QK_SMEM 139264

__global__ void __launch_bounds__(512, 1)
qk_mma_kernel(const float* __restrict__ Wq, const float* __restrict__ Wk) {
    extern __shared__ char smc[];
    uint32_t* AH = (uint32_t*)(smc + QK_AH);
    uint32_t* AL = (uint32_t*)(smc + QK_AL);
    uint32_t* BH = (uint32_t*)(smc + QK_BH);
    uint32_t* BL = (uint32_t*)(smc + QK_BL);
    const int t = threadIdx.x;
    const int wid = t >> 5, lane = t & 31;
    const int gid = lane >> 2, tig = lane & 3;
    const int rowgrp = wid & 7, colhalf = wid >> 3;
    const int bx = blockIdx.x, by = blockIdx.y;

    #pragma unroll
    for (int i = 0; i < 16; i++) {
        int w = t + i*512;
        int row = w >> 6, k2 = w & 63;
        float2 va = *(const float2*)(g_x + (size_t)(bx*128 + row)*128 + k2*2);
        uint32_t hi, lo; split_pair(va.x, va.y, hi, lo);
        AH[row*PS + k2] = hi; AL[row*PS + k2] = lo;
        int o = by*128 + row;
        const float* wr = (o < 1024) ? (Wq + (size_t)o*128) : (Wk + (size_t)(o-1024)*128);
        float2 vb = *(const float2*)(wr + k2*2);
        split_pair(vb.x, vb.y, hi, lo);
        BH[row*PS + k2] = hi; BL[row*PS + k2] = lo;
    }
    __syncthreads();

    const int r0 = rowgrp*16 + gid, r1 = r0 + 8;
    float acc[8][4];
    #pragma unroll
    for (int n = 0; n < 8; n++)
        #pragma unroll
        for (int u = 0; u < 4; u++) acc[n][u] = 0.f;

    #pragma unroll
    for (int ks = 0; ks < 8; ks++) {
        int ca = 8*ks + tig;
        uint32_t aH[4], aL[4];
        aH[0] = AH[r0*PS + ca];     aH[1] = AH[r1*PS + ca];
        aH[2] = AH[r0*PS + ca + 4]; aH[3] = AH[r1*PS + ca + 4];
        aL[0] = AL[r0*PS + ca];     aL[1] = AL[r1*PS + ca];
        aL[2] = AL[r0*PS + ca + 4]; aL[3] = AL[r1*PS + ca + 4];
        uint32_t bf[8][2];
        #pragma unroll
        for (int n = 0; n < 8; n++) {
            int nb = (8*(colhalf*8 + n) + gid)*PS + ca;
            bf[n][0] = BH[nb]; bf[n][1] = BH[nb + 4];
        }
        #pragma unroll
        for (int n = 0; n < 8; n++) mma_bf16(acc[n], aH, bf[n]);
        #pragma unroll
        for (int n = 0; n < 8; n++) mma_bf16(acc[n], aL, bf[n]);
        #pragma unroll
        for (int n = 0; n < 8; n++) {
            int nb = (8*(colhalf*8 + n) + gid)*PS + ca;
            bf[n][0] = BL[nb]; bf[n][1] = BL[nb + 4];
        }
        #pragma unroll
        for (int n = 0; n < 8; n++) mma_bf16(acc[n], aH, bf[n]);
    }

    #pragma unroll
    for (int n = 0; n < 8; n++) {
        int nt = colhalf*8 + n;
        int cn = 8*nt + 2*tig;
        int colg = by*128 + cn;
        size_t ra = (size_t)(bx*128 + r0), rb = (size_t)(bx*128 + r1);
        if (by < 8) {
            *(float2*)(g_q + ra*1024 + colg)          = make_float2(acc[n][0], acc[n][1]);
            *(float2*)(g_q + rb*1024 + colg)          = make_float2(acc[n][2], acc[n][3]);
        } else {
            *(float2*)(g_k + ra*1024 + (colg - 1024)) = make_float2(acc[n][0], acc[n][1]);
            *(float2*)(g_k + rb*1024 + (colg - 1024)) = make_float2(acc[n][2], acc[n][3]);
        }
    }
}

// ================================================ FUSED attention kernel
// CTA = (mt, h, b), 512 threads / 16 warps.
// Per 128-col chunk: S = Q·K^T (3 chain-separated sweeps) -> exp in regs ->
// exp tile into K buffers (bf16 hi/lo) -> ctx += exp·X^T (3 sweeps).
// Unnormalized exp streamed to P; tail normalizes P in place (L2-hot) and
// scales ctx rows by 1/z.
#define FS_QH   0
#define FS_QL   34816
#define FS_KH   69632       // reused as A (exp tile) for ctx MMA
#define FS_KL   104448
#define FS_XH   139264
#define FS_XL   174080
#define FS_RR   208896      // bf16 128x32
#define FS_RC   217088      // bf16 128x32
#define FS_ZP   225280      // fp32 256
#define FS_RZ   226304      // fp32 128
#define FS_SMEM 226816

__global__ void __launch_bounds__(512, 1)
attn_fused(const float* __restrict__ row_emb, const float* __restrict__ col_emb,
           float* __restrict__ P)
{
    extern __shared__ char smc[];
    uint32_t* QH = (uint32_t*)(smc + FS_QH);
    uint32_t* QL = (uint32_t*)(smc + FS_QL);
    uint32_t* KH = (uint32_t*)(smc + FS_KH);
    uint32_t* KL = (uint32_t*)(smc + FS_KL);
    uint32_t* XH = (uint32_t*)(smc + FS_XH);
    uint32_t* XL = (uint32_t*)(smc + FS_XL);
    __nv_bfloat16* RR = (__nv_bfloat16*)(smc + FS_RR);
    __nv_bfloat16* RC = (__nv_bfloat16*)(smc + FS_RC);
    float* ZP = (float*)(smc + FS_ZP);
    float* RZ = (float*)(smc + FS_RZ);

    const int t = threadIdx.x;
    const int wid = t >> 5, lane = t & 31;
    const int gid = lane >> 2, tig = lane & 3;
    const int rowgrp = wid & 7, colhalf = wid >> 3;
    const int mt = blockIdx.x, h = blockIdx.y, b = blockIdx.z;

    const float* qb = g_q + ((size_t)b*1024 + mt*128)*1024 + h*128;

    // Q tile -> smem hi/lo
    #pragma unroll
    for (int i = 0; i < 16; i++) {
        int w = t + i*512;
        int row = w >> 6, k2 = w & 63;
        float2 v = *(const float2*)(qb + (size_t)row*1024 + k2*2);
        uint32_t hi, lo; split_pair(v.x, v.y, hi, lo);
        QH[row*PS + k2] = hi; QL[row*PS + k2] = lo;
    }
    // relative-position terms (fp32 math, bf16 storage)
    for (int w = t; w < 8192; w += 512) {
        if (w < 4096) {
            int row = w >> 5, k = w & 31;
            int ig = (mt*128 + row) >> 5;
            const float* e  = row_emb + (k - ig + 31)*64;
            const float* qv = qb + (size_t)row*1024;
            float s = 0.f;
            #pragma unroll 16
            for (int d = 0; d < 64; d++) s += qv[d]*e[d];
            RR[row*32 + k] = __float2bfloat16(s);
        } else {
            int w2 = w - 4096;
            int row = w2 >> 5, l = w2 & 31;
            int jg = (mt*128 + row) & 31;
            const float* e  = col_emb + (l - jg + 31)*64;
            const float* qv = qb + (size_t)row*1024 + 64;
            float s = 0.f;
            #pragma unroll 16
            for (int d = 0; d < 64; d++) s += qv[d]*e[d];
            RC[row*32 + l] = __float2bfloat16(s);
        }
    }

    const float*    kb = g_k + (size_t)b*1024*1024 + h*128;
    const uint32_t* xh = (const uint32_t*)g_xth;
    const uint32_t* xl = (const uint32_t*)g_xtl;

    const int r0 = rowgrp*16 + gid, r1 = r0 + 8;
    const int rg0 = mt*128 + r0, rg1 = mt*128 + r1;
    float* prow0 = P + ((((size_t)b*32 + (rg0 & 31))*32 + (rg0 >> 5))*8 + h)*1024;
    float* prow1 = P + ((((size_t)b*32 + (rg1 & 31))*32 + (rg1 >> 5))*8 + h)*1024;
    float z0 = 0.f, z1 = 0.f;

    float cacc[8][4];
    #pragma unroll
    for (int n = 0; n < 8; n++)
        #pragma unroll
        for (int u = 0; u < 4; u++) cacc[n][u] = 0.f;

    for (int c = 0; c < 8; c++) {
        __syncthreads();   // prev ctx MMA done reading A/X (and Q/rel stores at c=0)
        // K chunk -> KH/KL
        #pragma unroll
        for (int i = 0; i < 16; i++) {
            int w = t + i*512;
            int np = w >> 6, k2 = w & 63;
            int n = c*128 + np;
            int src = (n & 31)*32 + (n >> 5);
            float2 v = *(const float2*)(kb + (size_t)src*1024 + k2*2);
            uint32_t hi, lo; split_pair(v.x, v.y, hi, lo);
            KH[np*PS + k2] = hi; KL[np*PS + k2] = lo;
        }
        // X^T chunk -> XH/XL
        #pragma unroll
        for (int i = 0; i < 16; i++) {
            int w = t + i*512;
            int dp = w >> 6, k2 = w & 63;
            size_t idx = ((size_t)b*128 + dp)*512 + c*64 + k2;   // uint32 units
            XH[dp*PS + k2] = xh[idx];
            XL[dp*PS + k2] = xl[idx];
        }
        __syncthreads();

        // ---- scores MMA: S = Q · K^T  (chain-separated sweeps, dep distance 8)
        float sacc[8][4];
        #pragma unroll
        for (int n = 0; n < 8; n++)
            #pragma unroll
            for (int u = 0; u < 4; u++) sacc[n][u] = 0.f;
        #pragma unroll
        for (int ks = 0; ks < 8; ks++) {
            int ca = 8*ks + tig;
            uint32_t aH[4], aL[4];
            aH[0] = QH[r0*PS + ca];     aH[1] = QH[r1*PS + ca];
            aH[2] = QH[r0*PS + ca + 4]; aH[3] = QH[r1*PS + ca + 4];
            aL[0] = QL[r0*PS + ca];     aL[1] = QL[r1*PS + ca];
            aL[2] = QL[r0*PS + ca + 4]; aL[3] = QL[r1*PS + ca + 4];
            uint32_t bf[8][2];
            #pragma unroll
            for (int n = 0; n < 8; n++) {
                int nb = (8*(colhalf*8 + n) + gid)*PS + ca;
                bf[n][0] = KH[nb]; bf[n][1] = KH[nb + 4];
            }
            #pragma unroll
            for (int n = 0; n < 8; n++) mma_bf16(sacc[n], aH, bf[n]);
            #pragma unroll
            for (int n = 0; n < 8; n++) mma_bf16(sacc[n], aL, bf[n]);
            #pragma unroll
            for (int n = 0; n < 8; n++) {
                int nb = (8*(colhalf*8 + n) + gid)*PS + ca;
                bf[n][0] = KL[nb]; bf[n][1] = KL[nb + 4];
            }
            #pragma unroll
            for (int n = 0; n < 8; n++) mma_bf16(sacc[n], aH, bf[n]);
        }

        // ---- epilogue: exp, z, stream unnormalized P, keep bf16 hi/lo
        uint32_t eh0[8], el0[8], eh1[8], el1[8];
        #pragma unroll
        for (int n = 0; n < 8; n++) {
            int nt = colhalf*8 + n;
            int cn = 8*nt + 2*tig;
            int cg = c*128 + cn;
            int l = cg >> 5;
            int k0 = cg & 31, k1 = k0 + 1;
            float rcr0 = __bfloat162float(RC[r0*32 + l]);
            float rcr1 = __bfloat162float(RC[r1*32 + l]);
            float p00 = __expf(SCALE*(sacc[n][0] + __bfloat162float(RR[r0*32 + k0]) + rcr0));
            float p01 = __expf(SCALE*(sacc[n][1] + __bfloat162float(RR[r0*32 + k1]) + rcr0));
            float p10 = __expf(SCALE*(sacc[n][2] + __bfloat162float(RR[r1*32 + k0]) + rcr1));
            float p11 = __expf(SCALE*(sacc[n][3] + __bfloat162float(RR[r1*32 + k1]) + rcr1));
            z0 += p00 + p01;
            z1 += p10 + p11;
            *(float2*)(prow0 + cg) = make_float2(p00, p01);
            *(float2*)(prow1 + cg) = make_float2(p10, p11);
            split_pair(p00, p01, eh0[n], el0[n]);
            split_pair(p10, p11, eh1[n], el1[n]);
        }
        __syncthreads();   // all warps done with K reads for scores
        // exp tile -> KH/KL (A operand for ctx MMA)
        #pragma unroll
        for (int n = 0; n < 8; n++) {
            int nt = colhalf*8 + n;
            int k2 = 4*nt + tig;      // pair index of cols (8nt+2tig, +1)
            KH[r0*PS + k2] = eh0[n];  KL[r0*PS + k2] = el0[n];
            KH[r1*PS + k2] = eh1[n];  KL[r1*PS + k2] = el1[n];
        }
        __syncthreads();

        // ---- ctx MMA: cacc += exp · X^T  (chain-separated sweeps)
        #pragma unroll
        for (int ks = 0; ks < 8; ks++) {
            int ca = 8*ks + tig;
            uint32_t aH[4], aL[4];
            aH[0] = KH[r0*PS + ca];     aH[1] = KH[r1*PS + ca];
            aH[2] = KH[r0*PS + ca + 4]; aH[3] = KH[r1*PS + ca + 4];
            aL[0] = KL[r0*PS + ca];     aL[1] = KL[r1*PS + ca];
            aL[2] = KL[r0*PS + ca + 4]; aL[3] = KL[r1*PS + ca + 4];
            uint32_t bf[8][2];
            #pragma unroll
            for (int n = 0; n < 8; n++) {
                int nb = (8*(colhalf*8 + n) + gid)*PS + ca;
                bf[n][0] = XH[nb]; bf[n][1] = XH[nb + 4];
            }
            #pragma unroll
            for (int n = 0; n < 8; n++) mma_bf16(cacc[n], aH, bf[n]);
            #pragma unroll
            for (int n = 0; n < 8; n++) mma_bf16(cacc[n], aL, bf[n]);
            #pragma unroll
            for (int n = 0; n < 8; n++) {
                int nb = (8*(colhalf*8 + n) + gid)*PS + ca;
                bf[n][0] = XL[nb]; bf[n][1] = XL[nb + 4];
            }
            #pragma unroll
            for (int n = 0; n < 8; n++) mma_bf16(cacc[n], aH, bf[n]);
        }
    }

    // ---- z reduction -> RZ
    z0 += __shfl_xor_sync(0xffffffffu, z0, 1);
    z0 += __shfl_xor_sync(0xffffffffu, z0, 2);
    z1 += __shfl_xor_sync(0xffffffffu, z1, 1);
    z1 += __shfl_xor_sync(0xffffffffu, z1, 2);
    if (tig == 0) {
        ZP[colhalf*128 + r0] = z0;
        ZP[colhalf*128 + r1] = z1;
    }
    __syncthreads();
    if (t < 128) RZ[t] = 1.0f / (ZP[t] + ZP[128 + t]);
    __syncthreads();

    // ---- ctx epilogue: scale by 1/z, write g_ctx (row r2 = j*32 + i)
    {
        float s0 = RZ[r0], s1 = RZ[r1];
        int r2a = (rg0 & 31)*32 + (rg0 >> 5);
        int r2b = (rg1 & 31)*32 + (rg1 >> 5);
        float* oa = g_ctx + ((size_t)b*1024 + r2a)*1024 + h*128;
        float* ob = g_ctx + ((size_t)b*1024 + r2b)*1024 + h*128;
        #pragma unroll
        for (int n = 0; n < 8; n++) {
            int cn = 8*(colhalf*8 + n) + 2*tig;
            *(float2*)(oa + cn) = make_float2(cacc[n][0]*s0, cacc[n][1]*s0);
            *(float2*)(ob + cn) = make_float2(cacc[n][2]*s1, cacc[n][3]*s1);
        }
    }

    // ---- tail: normalize this CTA's P rows in place (L2-hot)
    #pragma unroll
    for (int it = 0; it < 64; it++) {
        int w = t + it*512;                  // 32768 float4s
        int row = w >> 8, c4 = w & 255;
        int rg = mt*128 + row;
        float rz = RZ[row];
        float4* addr = (float4*)(P + ((((size_t)b*32 + (rg & 31))*32 + (rg >> 5))*8 + h)*1024) + c4;
        float4 v = *addr;
        v.x *= rz; v.y *= rz; v.z *= rz; v.w *= rz;
        *addr = v;
    }
}

// ================================================ tensorized output projection
#define OU_AH   0
#define OU_AL   17408
#define OU_BH   34816
#define OU_BL   69632
#define OU_SMEM 104448

__global__ void __launch_bounds__(512, 1)
out_mma_kernel(const float* __restrict__ Wv, const float* __restrict__ bv,
               float* __restrict__ out)
{
    extern __shared__ char smc[];
    uint32_t* AH = (uint32_t*)(smc + OU_AH);
    uint32_t* AL = (uint32_t*)(smc + OU_AL);
    uint32_t* BH = (uint32_t*)(smc + OU_BH);
    uint32_t* BL = (uint32_t*)(smc + OU_BL);

    const int t = threadIdx.x;
    const int wid = t >> 5, lane = t & 31;
    const int gid = lane >> 2, tig = lane & 3;
    const int rowgrp = wid & 3, colq = wid >> 2;
    const int bx = blockIdx.x;

    float acc[4][4];
    #pragma unroll
    for (int n = 0; n < 4; n++)
        #pragma unroll
        for (int u = 0; u < 4; u++) acc[n][u] = 0.f;

    const int r0 = rowgrp*16 + gid, r1 = r0 + 8;

    for (int c = 0; c < 8; c++) {
        __syncthreads();
        #pragma unroll
        for (int i = 0; i < 8; i++) {
            int w = t + i*512;
            int row = w >> 6, k2 = w & 63;
            float2 v = *(const float2*)(g_ctx + (size_t)(bx*64 + row)*1024 + c*128 + k2*2);
            uint32_t hi, lo; split_pair(v.x, v.y, hi, lo);
            AH[row*PS + k2] = hi; AL[row*PS + k2] = lo;
        }
        #pragma unroll
        for (int i = 0; i < 16; i++) {
            int w = t + i*512;
            int o = w >> 6, k2 = w & 63;
            float2 v = *(const float2*)(Wv + (size_t)o*1024 + c*128 + k2*2);
            uint32_t hi, lo; split_pair(v.x, v.y, hi, lo);
            BH[o*PS + k2] = hi; BL[o*PS + k2] = lo;
        }
        __syncthreads();

        #pragma unroll
        for (int ks = 0; ks < 8; ks++) {
            int ca = 8*ks + tig;
            uint32_t aH[4], aL[4];
            aH[0] = AH[r0*PS + ca];     aH[1] = AH[r1*PS + ca];
            aH[2] = AH[r0*PS + ca + 4]; aH[3] = AH[r1*PS + ca + 4];
            aL[0] = AL[r0*PS + ca];     aL[1] = AL[r1*PS + ca];
            aL[2] = AL[r0*PS + ca + 4]; aL[3] = AL[r1*PS + ca + 4];
            uint32_t bf[4][2];
            #pragma unroll
            for (int n = 0; n < 4; n++) {
                int nb = (8*(colq*4 + n) + gid)*PS + ca;
                bf[n][0] = BH[nb]; bf[n][1] = BH[nb + 4];
            }
            #pragma unroll
            for (int n = 0; n < 4; n++) mma_bf16(acc[n], aH, bf[n]);
            #pragma unroll
            for (int n = 0; n < 4; n++) mma_bf16(acc[n], aL, bf[n]);
            #pragma unroll
            for (int n = 0; n < 4; n++) {
                int nb = (8*(colq*4 + n) + gid)*PS + ca;
                bf[n][0] = BL[nb]; bf[n][1] = BL[nb + 4];
            }
            #pragma unroll
            for (int n = 0; n < 4; n++) mma_bf16(acc[n], aH, bf[n]);
        }
    }

    {
        size_t ra = (size_t)(bx*64 + r0), rb = (size_t)(bx*64 + r1);
        #pragma unroll
        for (int n = 0; n < 4; n++) {
            int o = 8*(colq*4 + n) + 2*tig;
            float b0 = bv[o], b1 = bv[o+1];
            float2 xa = *(const float2*)(g_x + ra*128 + o);
            float2 xb = *(const float2*)(g_x + rb*128 + o);
            *(float2*)(out + ra*128 + o) = make_float2(acc[n][0] + b0 + xa.x,
                                                       acc[n][1] + b1 + xa.y);
            *(float2*)(out + rb*128 + o) = make_float2(acc[n][2] + b0 + xb.x,
                                                       acc[n][3] + b1 + xb.y);
        }
    }
}

// ---------------------------------------------------------------- launcher
extern "C" void kernel_launch(void* const* d_in, const int* in_sizes, int n_in,
                              void* d_out, int out_size) {
    const float* hs      = (const float*)d_in[0];
    const float* row_emb = (const float*)d_in[1];
    const float* col_emb = (const float*)d_in[2];
    const float* Wq      = (const float*)d_in[3];
    const float* Wk      = (const float*)d_in[4];
    const float* Wv      = (const float*)d_in[5];
    const float* bv      = (const float*)d_in[6];
    const float* ln_g    = (const float*)d_in[7];
    const float* ln_b    = (const float*)d_in[8];
    float* out = (float*)d_out;

    int write_probs = (out_size >= 1048576 + 67108864) ? 1 : 0;
    float* P;
    if (write_probs) {
        P = out + 1048576;
    } else {
        cudaGetSymbolAddress((void**)&P, g_pscratch);
    }

    cudaFuncSetAttribute(qk_mma_kernel,  cudaFuncAttributeMaxDynamicSharedMemorySize, QK_SMEM);
    cudaFuncSetAttribute(attn_fused,     cudaFuncAttributeMaxDynamicSharedMemorySize, FS_SMEM);
    cudaFuncSetAttribute(out_mma_kernel, cudaFuncAttributeMaxDynamicSharedMemorySize, OU_SMEM);

    ln_kernel<<<8192, 128>>>(hs, ln_g, ln_b);

    dim3 gxt(32, 4, BSZ);
    xt_kernel<<<gxt, 256>>>();

    dim3 gqk(64, 16);
    qk_mma_kernel<<<gqk, 512, QK_SMEM>>>(Wq, Wk);

    dim3 gat(8, NHEADS, BSZ);
    attn_fused<<<gat, 512, FS_SMEM>>>(row_emb, col_emb, P);

    out_mma_kernel<<<128, 512, OU_SMEM>>>(Wv, bv, out);
}